// round 16
// baseline (speedup 1.0000x reference)
#include <cuda_runtime.h>
#include <cstdint>

typedef unsigned long long u64;

#define NI 128
#define NP 2000
#define MG 100
#define NA 2100
#define NAP 2112              // 16B-aligned per-image slab stride
#define NS 512
#define MAXPOS 128
#define NUMNEG 384
#define NB 2048
#define CHUNK 3               // 3*1024 >= 2100; boundary fixup at tid 42

#define K1_NT 256
#define K1_SPAN 525           // boxes per K1 CTA (4 CTAs per image)
#define K2_NT 1024
#define K2_GRID 160           // >=148 (grid-pad; extra CTAs exit)

// inter-kernel scratch (device globals: allocation-free)
__device__ unsigned char d_cls[NI * NAP + 16];   // shift: 42=pos, 21=neg-cand, 0=ignore
__device__ short         d_amax[NI * NAP + 8];

__device__ __forceinline__ void cp16(void* s, const void* g) {
    uint32_t sa = (uint32_t)__cvta_generic_to_shared(s);
    asm volatile("cp.async.cg.shared.global [%0], [%1], 16;" :: "r"(sa), "l"(g));
}

// ============================ KERNEL 1: classify ============================
// grid = 4*NI CTAs x 256 thr. Each CTA: one image quarter (525 boxes).
// Best tracked as exact (inter, union) pair; cross-mult compare ==
// exact-quotient argmax. RN division is monotone, so the final max IoU
// (threshold test) matches the reference bit-for-bit.
__global__ __launch_bounds__(K1_NT)
void k1_classify(const float4* __restrict__ g_rois,   // [NI, NP]
                 const float*  __restrict__ g_scores, // [NI, NP]
                 const float4* __restrict__ g_gt)     // [NI, MG]
{
    const int img  = blockIdx.x >> 2;
    const int base = (blockIdx.x & 3) * K1_SPAN;
    const int tid  = threadIdx.x;
    const unsigned lane = tid & 31, wd = tid >> 5;

    __shared__ float4 vbox[MG];
    __shared__ float  varea[MG];
    __shared__ short  vidx[MG];
    __shared__ int    wcnt[4];
    __shared__ int    sV;

    // gt load + validity. Zero-area gt gives IoU == 0.0f exactly vs every box
    // (clip algebra), so skipping them is bit-exact given best=0 / arg=0 init.
    float4 myb; float myar = 0.f; bool myval = false;
    if (tid < MG) {
        myb = g_gt[(size_t)img * MG + tid];
        myar = fmaxf(myb.z - myb.x, 0.f) * fmaxf(myb.w - myb.y, 0.f);
        myval = myar > 0.f;
    }
    unsigned bal = __ballot_sync(0xFFFFFFFFu, myval);
    if (lane == 0 && wd < 4) wcnt[wd] = __popc(bal);
    __syncthreads();
    if (myval) {                      // compact valid gt (order-preserving)
        int off = __popc(bal & ((1u << lane) - 1));
        for (int w = 0; w < (int)wd; ++w) off += wcnt[w];
        vbox[off] = myb; varea[off] = myar; vidx[off] = (short)tid;
    }
    if (tid == 0) sV = wcnt[0] + wcnt[1] + wcnt[2] + wcnt[3];
    __syncthreads();
    const int V = sV;

    const float4* rp = g_rois   + (size_t)img * NP;
    const float*  sp = g_scores + (size_t)img * NP;
    const float4* gp = g_gt     + (size_t)img * MG;
    unsigned char* cp = d_cls  + (size_t)img * NAP;
    short*         ap = d_amax + (size_t)img * NAP;

    // dual-box classify (2 indep dep chains per thread)
    {
        const int i0 = base + tid, i1 = i0 + K1_NT;
        float4 b0 = (i0 < NP) ? rp[i0] : gp[i0 - NP];
        float4 b1 = (i1 < NP) ? rp[i1] : gp[i1 - NP];
        float  s0 = (i0 < NP) ? sp[i0] : 1.f;
        float  s1 = (i1 < NP) ? sp[i1] : 1.f;
        float aa0 = fmaxf(b0.z - b0.x, 0.f) * fmaxf(b0.w - b0.y, 0.f);
        float aa1 = fmaxf(b1.z - b1.x, 0.f) * fmaxf(b1.w - b1.y, 0.f);
        float bi0 = 0.f, bu0 = 1.f, bi1 = 0.f, bu1 = 1.f;
        int a0 = 0, a1 = 0;
        #pragma unroll 2
        for (int m = 0; m < V; ++m) {
            float4 g  = vbox[m];
            float  ar = varea[m];
            float w, h, in, un;
            w = fminf(b0.z, g.z) - fmaxf(b0.x, g.x);
            h = fminf(b0.w, g.w) - fmaxf(b0.y, g.y);
            in = fmaxf(w, 0.f) * fmaxf(h, 0.f);   // == ref clip product
            un = (aa0 + ar) - in;                 // == ref union
            if (in * bu0 > bi0 * un) { bi0 = in; bu0 = un; a0 = m; }
            w = fminf(b1.z, g.z) - fmaxf(b1.x, g.x);
            h = fminf(b1.w, g.w) - fmaxf(b1.y, g.y);
            in = fmaxf(w, 0.f) * fmaxf(h, 0.f);
            un = (aa1 + ar) - in;
            if (in * bu1 > bi1 * un) { bi1 = in; bu1 = un; a1 = m; }
        }
        float q0 = __fdiv_rn(bi0, bu0);   // IEEE div once per box: bit-match JAX max
        float q1 = __fdiv_rn(bi1, bu1);
        cp[i0] = (q0 >= 0.5f) ? 42 : ((s0 < 0.f) ? 0 : 21);
        cp[i1] = (q1 >= 0.5f) ? 42 : ((s1 < 0.f) ? 0 : 21);
        ap[i0] = vidx[a0];                // remap compacted -> original gt idx
        ap[i1] = vidx[a1];
    }
    if (tid < K1_SPAN - 2 * K1_NT) {      // 13-box tail
        const int i2 = base + 2 * K1_NT + tid;
        float4 b = (i2 < NP) ? rp[i2] : gp[i2 - NP];
        float  s = (i2 < NP) ? sp[i2] : 1.f;
        float aa = fmaxf(b.z - b.x, 0.f) * fmaxf(b.w - b.y, 0.f);
        float bi = 0.f, bu = 1.f; int a = 0;
        for (int m = 0; m < V; ++m) {
            float4 g  = vbox[m];
            float  ar = varea[m];
            float w = fminf(b.z, g.z) - fmaxf(b.x, g.x);
            float h = fminf(b.w, g.w) - fmaxf(b.y, g.y);
            float in = fmaxf(w, 0.f) * fmaxf(h, 0.f);
            float un = (aa + ar) - in;
            if (in * bu > bi * un) { bi = in; bu = un; a = m; }
        }
        float q = __fdiv_rn(bi, bu);
        cp[i2] = (q >= 0.5f) ? 42 : ((s < 0.f) ? 0 : 21);
        ap[i2] = vidx[a];
    }
}

// ====================== KERNEL 2: sort + select + output ======================
struct __align__(16) K2Smem {
    u64    skey[NA];            // 16800 (final sorted keys)
    u64    tmp[NA];             // 16800 (arrival-order scatter)
    int    cnt[NB];             // 8192
    int    off[NB];             // 8192
    short  amax[NAP];           // 4224 (cp.async slab)
    unsigned char cls[NAP + 16];// 2128 (cp.async slab)
    int    iwsum[32];
    u64    wsum[32];
    u64    totals, ebound;
};

__global__ __launch_bounds__(K2_NT)
void k2_select(const float4* __restrict__ g_rois,   // [NI, NP]
               const float4* __restrict__ g_gt,     // [NI, MG]
               const float*  __restrict__ g_rand,   // [NI, NA]
               float* __restrict__ out)
{
    if (blockIdx.x >= NI) return;       // grid padding CTAs

    extern __shared__ char smem_raw[];
    K2Smem* sm = reinterpret_cast<K2Smem*>(smem_raw);

    const int img = blockIdx.x;
    const int tid = threadIdx.x;
    const unsigned lane = tid & 31, wd = tid >> 5;

    // prefetch cls/amax slabs produced by k1 (16B-aligned, strided NAP)
    if (tid < NAP / 16)
        cp16(&sm->cls[tid * 16], d_cls + (size_t)img * NAP + tid * 16);
    if (tid < NAP * 2 / 16)
        cp16(&((char*)sm->amax)[tid * 16], (const char*)(d_amax + (size_t)img * NAP) + tid * 16);
    asm volatile("cp.async.commit_group;");

    // zero histogram
    sm->cnt[tid] = 0; sm->cnt[tid + K2_NT] = 0;

    // keys: (rand_bits << 32) | idx. rand in [0,1): positive float bit
    // pattern is order-preserving; embedded idx makes ties stable AND keys
    // globally unique, so sorting these u64s == jnp.argsort(rand) exactly.
    u64 myk[3]; int mybkt[3]; int nown = 0;
    const float* rp = g_rand + (size_t)img * NA;
    #pragma unroll
    for (int e = 0; e < 3; ++e) {
        int i = tid + e * K2_NT;
        if (i < NA) {
            float r = rp[i];
            myk[e] = ((u64)__float_as_uint(r) << 32) | (unsigned int)i;
            // uniform value -> order-preserving bucket (monotone fp ops)
            mybkt[e] = min((int)(r * (float)NB), NB - 1);
            ++nown;
        }
    }
    __syncthreads();                    // zeroed cnt visible

    #pragma unroll
    for (int e = 0; e < 3; ++e)
        if (e < nown) atomicAdd(&sm->cnt[mybkt[e]], 1);
    __syncthreads();

    // exclusive scan of 2048 bins: 2 consecutive bins per thread
    {
        int c0 = sm->cnt[2 * tid], c1 = sm->cnt[2 * tid + 1];
        int s2 = c0 + c1;
        int vv = s2;
        #pragma unroll
        for (int o = 1; o < 32; o <<= 1) {
            int n = __shfl_up_sync(0xFFFFFFFFu, vv, o);
            if (lane >= (unsigned)o) vv += n;
        }
        if (lane == 31) sm->iwsum[wd] = vv;
        __syncthreads();
        if (tid < 32) {                 // warp-parallel cross-warp scan
            int t0 = sm->iwsum[tid];
            int tv = t0;
            #pragma unroll
            for (int o = 1; o < 32; o <<= 1) {
                int n = __shfl_up_sync(0xFFFFFFFFu, tv, o);
                if (lane >= (unsigned)o) tv += n;
            }
            sm->iwsum[tid] = tv - t0;   // exclusive
        }
        __syncthreads();
        int ex = sm->iwsum[wd] + (vv - s2);
        sm->off[2 * tid]     = ex;
        sm->off[2 * tid + 1] = ex + c0;
    }
    __syncthreads();

    // scatter keys into bucket slots in arrival order (off[b] -> END)
    #pragma unroll
    for (int e = 0; e < 3; ++e)
        if (e < nown) {
            int p = atomicAdd(&sm->off[mybkt[e]], 1);
            sm->tmp[p] = myk[e];
        }
    __syncthreads();

    // element-parallel rank-scatter (keys unique -> exact rank)
    #pragma unroll
    for (int e = 0; e < 3; ++e)
        if (e < nown) {
            int b   = mybkt[e];
            int end = sm->off[b];
            int beg = end - sm->cnt[b];
            u64 key = myk[e];
            int rank = 0;
            for (int q = beg; q < end; ++q)
                rank += (sm->tmp[q] < key);
            sm->skey[beg + rank] = key;
        }

    asm volatile("cp.async.wait_group 0;");
    __syncthreads();                    // skey + cls/amax slabs visible

    // ---- packed per-class stable-rank scan (21-bit fields in one u64) ----
    // CHUNK=3: thread t covers j in [3t, 3t+3); covers all 2100 (<= 3072)
    const int j0 = tid * CHUNK;
    unsigned int idxr[CHUNK]; int shr[CHUNK];
    int nj = 0;
    u64 loc = 0;
    #pragma unroll
    for (int e = 0; e < CHUNK; ++e) {
        int j = j0 + e;
        if (j < NA) {
            unsigned int idx = (unsigned int)sm->skey[j];
            int sh = sm->cls[idx];
            idxr[e] = idx; shr[e] = sh;
            loc += 1ull << sh;
            ++nj;
        }
    }
    u64 v = loc;
    #pragma unroll
    for (int o = 1; o < 32; o <<= 1) {
        u64 n = __shfl_up_sync(0xFFFFFFFFu, v, o);
        if (lane >= (unsigned)o) v += n;
    }
    if (lane == 31) sm->wsum[wd] = v;
    __syncthreads();
    if (tid < 32) {
        u64 t0 = sm->wsum[tid];
        u64 tv = t0;
        #pragma unroll
        for (int o = 1; o < 32; o <<= 1) {
            u64 n = __shfl_up_sync(0xFFFFFFFFu, tv, o);
            if (lane >= (unsigned)o) tv += n;
        }
        sm->wsum[tid] = tv - t0;        // exclusive
        if (tid == 31) sm->totals = tv; // inclusive total
    }
    __syncthreads();
    const u64 excl = sm->wsum[wd] + (v - loc);
    // MAXPOS=128 boundary falls inside thread 42's chunk (j=126,127,128):
    // ebound = prefix over j in [0,128) = excl + cls(126) + cls(127)
    if (tid == MAXPOS / CHUNK)
        sm->ebound = excl + (1ull << shr[0]) + (1ull << shr[1]);
    __syncthreads();

    // ---- closed-form slot assignment + output ----
    const u64 M21 = (1ull << 21) - 1;
    const u64 tot = sm->totals, ev = sm->ebound;
    const int c3  = (int)((tot >> 42) & M21);
    const int c2t = (int)((tot >> 21) & M21);
    const int e3  = (int)((ev  >> 42) & M21);
    const int e2  = (int)((ev  >> 21) & M21);
    const int e0  = (int)( ev         & M21);
    const int d2 = c2t - e2, d3 = c3 - e3;

    int r3 = (int)((excl >> 42) & M21);
    int r2 = (int)((excl >> 21) & M21);
    int r0 = (int)( excl         & M21);

    const float4* rpb = g_rois + (size_t)img * NP;
    const float4* gpb = g_gt   + (size_t)img * MG;
    float* out_rois    = out;
    float* out_samples = out + (size_t)NI * NS * 4;
    float* out_matches = out_samples + (size_t)NI * NS;

    #pragma unroll
    for (int e = 0; e < CHUNK; ++e) {
        if (e >= nj) break;
        const int j = j0 + e;
        unsigned int idx = idxr[e];
        int sh = shr[e];
        int r;
        if (sh == 42)      r = r3++;
        else if (sh == 21) r = r2++;
        else               r = r0++;

        // top partition: priority 3 > 2 > 0, stable in j, first MAXPOS
        int tb = (sh == 42) ? 0 : (sh == 21 ? c3 : (c3 + c2t));
        int pos = tb + r;
        int slot1 = (pos < MAXPOS) ? pos : -1;

        // bottom partition: among j>=MAXPOS, priority 2 > 3 > 0, first NUMNEG
        int slot2 = -1;
        if (j >= MAXPOS) {
            int ec = (sh == 42) ? e3 : (sh == 21 ? e2 : e0);
            int bb = (sh == 21) ? 0 : (sh == 42 ? d2 : (d2 + d3));
            int pos2 = bb + (r - ec);
            if (pos2 < NUMNEG) slot2 = MAXPOS + pos2;
        }

        if (slot1 >= 0 || slot2 >= 0) {
            float4 b = (idx < NP) ? rpb[idx] : gpb[idx - NP];  // L2-hot from k1
            float sval = (sh == 42) ? 1.f : (sh == 21 ? -1.f : 0.f);
            float mval = (float)sm->amax[idx];
            if (slot1 >= 0) {
                size_t o = (size_t)img * NS + slot1;
                ((float4*)out_rois)[o] = b;
                out_samples[o] = sval;
                out_matches[o] = mval;
            }
            if (slot2 >= 0) {
                size_t o = (size_t)img * NS + slot2;
                ((float4*)out_rois)[o] = b;
                out_samples[o] = sval;
                out_matches[o] = mval;
            }
        }
    }
}

extern "C" void kernel_launch(void* const* d_in, const int* in_sizes, int n_in,
                              void* d_out, int out_size) {
    const float4* rois   = (const float4*)d_in[0];  // [128, 2000, 4]
    const float*  scores = (const float*)d_in[1];   // [128, 2000, 1]
    const float4* gt     = (const float4*)d_in[2];  // [128, 100, 4]
    const float*  rnd    = (const float*)d_in[3];   // [128, 2100]
    float* out = (float*)d_out;

    const int k2_smem = (int)sizeof(K2Smem);
    static int configured = 0;
    if (!configured) {
        cudaFuncSetAttribute(k2_select,
                             cudaFuncAttributeMaxDynamicSharedMemorySize, k2_smem);
        configured = 1;
    }
    k1_classify<<<NI * 4, K1_NT>>>(rois, scores, gt);
    k2_select<<<K2_GRID, K2_NT, k2_smem>>>(rois, gt, rnd, out);
}